// round 14
// baseline (speedup 1.0000x reference)
#include <cuda_runtime.h>
#include <cuda_bf16.h>
#include <cstdint>

// ---------------------------------------------------------------------------
// Problem constants
// ---------------------------------------------------------------------------
#define BATCH   32768
#define IN_DIM  1024
#define XROW    3072      // x row stride (3*32*32)
#define EMBED   16
#define TINY    16
#define NEXP    4
#define OUTD    1000
#define KC      72        // padded K for the big GEMM (64 hg + 4 gate + 4 zero)

#define CH      16        // K per x chunk
#define NCHUNK  64        // 1024 / 16
#define RING_D  4         // cp.async ring depth

// ---------------------------------------------------------------------------
// smem layout (floats).  Phase 1: Ws + ring + small weights.
// Phase 2 overlays: As[128][76] on Ws, Wc[72][136] on ring.
// ---------------------------------------------------------------------------
#define OFF_WS    0                      // [16][1028]  = 16448
#define OFF_RING  16448                  // 4 x [128][20] = 10240
#define RING_SLOT 2560                   // 128*20
#define OFF_SW1   26688                  // 1024
#define OFF_SWG   27712                  // 64
#define OFF_SB1   27776                  // 64
#define OFF_SBE   27840                  // 16
#define OFF_SBG   27856                  // 4
#define SMEM_FLOATS 27860                // 111440 bytes -> 2 CTAs/SM

// ---------------------------------------------------------------------------
// Helpers
// ---------------------------------------------------------------------------
__device__ __forceinline__ float tf32r(float v) {
    unsigned u;
    asm("cvt.rna.tf32.f32 %0, %1;" : "=r"(u) : "f"(v));
    return __uint_as_float(u);
}

__device__ __forceinline__ void ffma2(unsigned long long& acc,
                                      unsigned long long a,
                                      unsigned long long b) {
    asm("fma.rn.f32x2 %0, %1, %2, %0;" : "+l"(acc) : "l"(a), "l"(b));
}

__device__ __forceinline__ void mma_tf32(float* c, const unsigned* a,
                                         unsigned b0, unsigned b1) {
    asm volatile(
        "mma.sync.aligned.m16n8k8.row.col.f32.tf32.tf32.f32 "
        "{%0,%1,%2,%3}, {%4,%5,%6,%7}, {%8,%9}, {%0,%1,%2,%3};"
        : "+f"(c[0]), "+f"(c[1]), "+f"(c[2]), "+f"(c[3])
        : "r"(a[0]), "r"(a[1]), "r"(a[2]), "r"(a[3]), "r"(b0), "r"(b1));
}

__device__ __forceinline__ void cp_async16(float* s, const float* g) {
    unsigned sa = (unsigned)__cvta_generic_to_shared(s);
    asm volatile("cp.async.ca.shared.global [%0], [%1], 16;" :: "r"(sa), "l"(g));
}

// ---------------------------------------------------------------------------
// Fused kernel.  One CTA = 128 batch rows, grid 256, 2 CTAs/SM (one wave).
//
// Phase 1 (embed):  e = relu(x @ We^T + be) via tf32 mma.  x streamed
//   global->smem with a depth-4 cp.async ring (K=16 chunks, 1 sync/chunk).
//   x enters the MMA un-rounded (HW truncates to tf32).  W_embed is
//   tf32(rna) in smem [16][1028] (conflict-free B frags).
// Phase 1 epilogue: gate softmax + expert hidden layer (exact fp32, f32x2),
//   A[128][72] = [gate*h | gate | 0] written to smem (tf32-rounded).
// Phase 2 (output GEMM): out_tile[128,1000] = A @ Wc[72,1008], Wc chunks of
//   N=128 built inline in smem from W2/b2 (tf32-rounded), 8 chunks.
// ---------------------------------------------------------------------------
__global__ void __launch_bounds__(256, 2)
k_fused(const float* __restrict__ x,
        const float* __restrict__ We, const float* __restrict__ be,
        const float* __restrict__ W1, const float* __restrict__ b1,
        const float* __restrict__ W2, const float* __restrict__ b2,
        const float* __restrict__ Wg, const float* __restrict__ bg,
        float* __restrict__ out) {
    extern __shared__ float sm[];
    float* Ws   = sm + OFF_WS;
    float* ring = sm + OFF_RING;
    float* sW1  = sm + OFF_SW1;
    float* sWg  = sm + OFF_SWG;
    float* sb1  = sm + OFF_SB1;
    float* sbe  = sm + OFF_SBE;
    float* sbg  = sm + OFF_SBG;

    const int tid  = threadIdx.x;
    const int wid  = tid >> 5, lane = tid & 31;
    const int tig  = lane & 3, grp = lane >> 2;
    const int arow0 = wid * 16 + grp;

    const float* xbase = x + (size_t)blockIdx.x * 128 * XROW;

    // --- issue cp.async preload of chunks 0..RING_D-2 first (longest latency)
    {
        const int r  = (2 * tid)     >> 2;   // thread covers 2 float4 slots
        const int c4 = (2 * tid)     &  3;
        const int r2 = (2 * tid + 1) >> 2;
        const int c42= (2 * tid + 1) &  3;
#pragma unroll
        for (int s = 0; s < RING_D - 1; s++) {
            cp_async16(ring + s * RING_SLOT + r  * 20 + c4 * 4,
                       xbase + (size_t)r  * XROW + s * CH + c4 * 4);
            cp_async16(ring + s * RING_SLOT + r2 * 20 + c42 * 4,
                       xbase + (size_t)r2 * XROW + s * CH + c42 * 4);
            asm volatile("cp.async.commit_group;");
        }
    }

    // --- small weights
    for (int i = tid; i < 1024; i += 256) sW1[i] = W1[i];
    if (tid < 64)       sWg[tid] = Wg[tid];
    else if (tid < 128) sb1[tid - 64] = b1[tid - 64];
    else if (tid < 144) sbe[tid - 128] = be[tid - 128];
    else if (tid < 148) sbg[tid - 144] = bg[tid - 144];

    // --- W_embed -> smem [16][1028], tf32(rna)
    for (int i = tid; i < 4096; i += 256) {
        float4 v = ((const float4*)We)[i];
        v.x = tf32r(v.x); v.y = tf32r(v.y); v.z = tf32r(v.z); v.w = tf32r(v.w);
        int row = i >> 8, c4 = i & 255;
        *(float4*)(Ws + row * 1028 + c4 * 4) = v;
    }

    float c[2][4];
#pragma unroll
    for (int nt = 0; nt < 2; nt++)
#pragma unroll
        for (int q = 0; q < 4; q++) c[nt][q] = 0.f;

    // ---------------- phase-1 mainloop ----------------
    const unsigned* wsu = (const unsigned*)Ws;
    {
        const int r  = (2 * tid)     >> 2;
        const int c4 = (2 * tid)     &  3;
        const int r2 = (2 * tid + 1) >> 2;
        const int c42= (2 * tid + 1) &  3;

        for (int kc = 0; kc < NCHUNK; kc++) {
            asm volatile("cp.async.wait_group 2;");
            __syncthreads();   // chunk kc visible everywhere; also fences
                               // weight STS on kc==0 and mma(kc-1) everywhere
            // refill slot (kc+3)&3 with chunk kc+3 (empty commit at tail
            // keeps wait_group counts consistent)
            if (kc + RING_D - 1 < NCHUNK) {
                float* slot = ring + ((kc + RING_D - 1) & (RING_D - 1)) * RING_SLOT;
                const float* src = xbase + (size_t)(kc + RING_D - 1) * CH;
                cp_async16(slot + r  * 20 + c4 * 4,  src + (size_t)r  * XROW + c4 * 4);
                cp_async16(slot + r2 * 20 + c42 * 4, src + (size_t)r2 * XROW + c42 * 4);
            }
            asm volatile("cp.async.commit_group;");

            const unsigned* asu =
                (const unsigned*)(ring + (kc & (RING_D - 1)) * RING_SLOT);
#pragma unroll
            for (int k8 = 0; k8 < 2; k8++) {
                const int k0 = k8 * 8 + tig;
                unsigned a[4];
                a[0] = asu[arow0 * 20 + k0];
                a[1] = asu[(arow0 + 8) * 20 + k0];
                a[2] = asu[arow0 * 20 + k0 + 4];
                a[3] = asu[(arow0 + 8) * 20 + k0 + 4];
                const int kg = kc * CH + k0;
                {
                    unsigned b0 = wsu[grp * 1028 + kg];
                    unsigned b1 = wsu[grp * 1028 + kg + 4];
                    mma_tf32(c[0], a, b0, b1);
                }
                {
                    unsigned b0 = wsu[(8 + grp) * 1028 + kg];
                    unsigned b1 = wsu[(8 + grp) * 1028 + kg + 4];
                    mma_tf32(c[1], a, b0, b1);
                }
            }
        }
    }
    __syncthreads();   // all mma done; Ws + ring regions may be reused

    // ---------------- phase-1 epilogue: build A[128][76] in smem -----------
    float* As = sm;    // overlays Ws (dead)
#pragma unroll
    for (int nt = 0; nt < 2; nt++) {
        int jb = nt * 8 + 2 * tig;
        *(float2*)(As + arow0 * 76 + jb)       = make_float2(c[nt][0], c[nt][1]);
        *(float2*)(As + (arow0 + 8) * 76 + jb) = make_float2(c[nt][2], c[nt][3]);
    }
    __syncthreads();

    if (tid < 128) {
        float e[EMBED];
#pragma unroll
        for (int q = 0; q < 4; q++) {
            float4 v = *(float4*)(As + tid * 76 + q * 4);
            e[q * 4 + 0] = fmaxf(v.x + sbe[q * 4 + 0], 0.f);
            e[q * 4 + 1] = fmaxf(v.y + sbe[q * 4 + 1], 0.f);
            e[q * 4 + 2] = fmaxf(v.z + sbe[q * 4 + 2], 0.f);
            e[q * 4 + 3] = fmaxf(v.w + sbe[q * 4 + 3], 0.f);
        }
        float g[NEXP];
#pragma unroll
        for (int ex = 0; ex < NEXP; ex++) {
            float s = sbg[ex];
#pragma unroll
            for (int j = 0; j < EMBED; j++) s += e[j] * sWg[ex * EMBED + j];
            g[ex] = s;
        }
        float mx = fmaxf(fmaxf(g[0], g[1]), fmaxf(g[2], g[3]));
        float den = 0.f;
#pragma unroll
        for (int ex = 0; ex < NEXP; ex++) { g[ex] = __expf(g[ex] - mx); den += g[ex]; }
        float inv = 1.0f / den;
#pragma unroll
        for (int ex = 0; ex < NEXP; ex++) g[ex] *= inv;

        float* Arow = As + tid * 76;
#pragma unroll
        for (int ex = 0; ex < NEXP; ex++) {
            unsigned long long acc[8];
            const ulonglong2* bp = (const ulonglong2*)(sb1 + ex * TINY);
#pragma unroll
            for (int h = 0; h < 4; h++) {
                ulonglong2 t = bp[h];
                acc[2 * h] = t.x; acc[2 * h + 1] = t.y;
            }
#pragma unroll
            for (int j = 0; j < EMBED; j++) {
                unsigned long long ej2;
                asm("mov.b64 %0, {%1, %1};" : "=l"(ej2) : "f"(e[j]));
                const ulonglong2* wp =
                    (const ulonglong2*)(sW1 + (ex * EMBED + j) * TINY);
#pragma unroll
                for (int h = 0; h < 4; h++) {
                    ulonglong2 w = wp[h];
                    ffma2(acc[2 * h], ej2, w.x);
                    ffma2(acc[2 * h + 1], ej2, w.y);
                }
            }
            float gx = g[ex];
            float o[16];
#pragma unroll
            for (int h = 0; h < 8; h++) {
                float lo, hi;
                asm("mov.b64 {%0,%1}, %2;" : "=f"(lo), "=f"(hi) : "l"(acc[h]));
                o[2 * h]     = tf32r(fmaxf(lo, 0.f) * gx);
                o[2 * h + 1] = tf32r(fmaxf(hi, 0.f) * gx);
            }
#pragma unroll
            for (int q = 0; q < 4; q++)
                *(float4*)(Arow + ex * TINY + q * 4) =
                    make_float4(o[4 * q], o[4 * q + 1], o[4 * q + 2], o[4 * q + 3]);
        }
        *(float4*)(Arow + 64) = make_float4(tf32r(g[0]), tf32r(g[1]),
                                            tf32r(g[2]), tf32r(g[3]));
        *(float4*)(Arow + 68) = make_float4(0.f, 0.f, 0.f, 0.f);
    }
    __syncthreads();

    // ---------------- phase 2: out = A @ Wc, 8 N-chunks of 128 -------------
    float* Wc = sm + OFF_RING;   // overlays ring (dead), [72][136]
    const int wm = wid & 3, wn = wid >> 2;
    const int mbase = wm * 32, nbase = wn * 64;
    const int mb = blockIdx.x;

    for (int nb = 0; nb < 8; nb++) {
        // build Wc chunk from W2/b2, tf32(rna)
#pragma unroll
        for (int i = tid; i < 72 * 32; i += 256) {
            int r = i / 32, c4v = i % 32;
            int col = nb * 128 + c4v * 4;
            float4 v = make_float4(0.f, 0.f, 0.f, 0.f);
            if (col < OUTD) {
                if (r < 64)      v = *(const float4*)(W2 + r * OUTD + col);
                else if (r < 68) v = *(const float4*)(b2 + (r - 64) * OUTD + col);
            }
            v.x = tf32r(v.x); v.y = tf32r(v.y); v.z = tf32r(v.z); v.w = tf32r(v.w);
            *(float4*)(Wc + r * 136 + c4v * 4) = v;
        }
        __syncthreads();

        float cc[2][8][4];
#pragma unroll
        for (int m = 0; m < 2; m++)
#pragma unroll
            for (int n = 0; n < 8; n++)
#pragma unroll
                for (int q = 0; q < 4; q++) cc[m][n][q] = 0.f;

#pragma unroll
        for (int k8 = 0; k8 < 9; k8++) {
            const int k0 = k8 * 8 + tig;
            unsigned a[2][4];
#pragma unroll
            for (int m = 0; m < 2; m++) {
                int r = mbase + m * 16 + grp;
                a[m][0] = __float_as_uint(As[r * 76 + k0]);
                a[m][1] = __float_as_uint(As[(r + 8) * 76 + k0]);
                a[m][2] = __float_as_uint(As[r * 76 + k0 + 4]);
                a[m][3] = __float_as_uint(As[(r + 8) * 76 + k0 + 4]);
            }
#pragma unroll
            for (int n8 = 0; n8 < 8; n8++) {
                int nc = nbase + n8 * 8 + grp;
                unsigned b0 = __float_as_uint(Wc[k0 * 136 + nc]);
                unsigned b1 = __float_as_uint(Wc[(k0 + 4) * 136 + nc]);
                mma_tf32(cc[0][n8], a[0], b0, b1);
                mma_tf32(cc[1][n8], a[1], b0, b1);
            }
        }
        __syncthreads();   // Wc reads done before next chunk overwrites

        // stores (reg-only): predicated float2, no straddle (OUTD even)
#pragma unroll
        for (int m = 0; m < 2; m++) {
            int gr = mb * 128 + mbase + m * 16 + grp;
#pragma unroll
            for (int n8 = 0; n8 < 8; n8++) {
                int gc = nb * 128 + nbase + n8 * 8 + 2 * tig;
                if (gc < OUTD) {
                    *(float2*)(out + (size_t)gr * OUTD + gc) =
                        make_float2(cc[0][n8][0], cc[0][n8][1]);
                    *(float2*)(out + (size_t)(gr + 8) * OUTD + gc) =
                        make_float2(cc[1][n8][2], cc[1][n8][3]);
                }
            }
        }
        // NOTE: second row-group store for m loop handled above via cc[1];
        // cc[0][n8][2..3] and cc[1][n8][0..1] are the remaining quadrants:
#pragma unroll
        for (int n8 = 0; n8 < 8; n8++) {
            int gc = nb * 128 + nbase + n8 * 8 + 2 * tig;
            if (gc < OUTD) {
                int gr0 = mb * 128 + mbase + grp;          // m=0 tile
                int gr1 = mb * 128 + mbase + 16 + grp;     // m=1 tile
                *(float2*)(out + (size_t)(gr0 + 8) * OUTD + gc) =
                    make_float2(cc[0][n8][2], cc[0][n8][3]);
                *(float2*)(out + (size_t)gr1 * OUTD + gc) =
                    make_float2(cc[1][n8][0], cc[1][n8][1]);
            }
        }
    }
}

// ---------------------------------------------------------------------------
// Launch
// ---------------------------------------------------------------------------
extern "C" void kernel_launch(void* const* d_in, const int* in_sizes, int n_in,
                              void* d_out, int out_size) {
    const float* x   = (const float*)d_in[0];
    const float* We  = (const float*)d_in[1];
    const float* be  = (const float*)d_in[2];
    const float* W1  = (const float*)d_in[3];
    const float* b1  = (const float*)d_in[4];
    const float* W2  = (const float*)d_in[5];
    const float* b2  = (const float*)d_in[6];
    const float* Wg  = (const float*)d_in[7];
    const float* bg  = (const float*)d_in[8];
    float* out = (float*)d_out;

    static bool attr_done = false;  // attribute setting only; deterministic
    if (!attr_done) {
        cudaFuncSetAttribute(k_fused, cudaFuncAttributeMaxDynamicSharedMemorySize,
                             SMEM_FLOATS * 4);
        attr_done = true;
    }

    k_fused<<<BATCH / 128, 256, SMEM_FLOATS * 4>>>(x, We, be, W1, b1, W2, b2,
                                                   Wg, bg, out);
}

// round 15
// speedup vs baseline: 1.2719x; 1.2719x over previous
#include <cuda_runtime.h>
#include <cuda_fp16.h>
#include <cstdint>

// ---------------------------------------------------------------------------
// Problem constants
// ---------------------------------------------------------------------------
#define BATCH   32768
#define XROW    3072      // x row stride (3*32*32)
#define EMBED   16
#define TINY    16
#define NEXP    4
#define OUTD    1000

// ---------------------------------------------------------------------------
// smem layout (float offsets).  Total 27924 floats = 111696 B -> 2 CTAs/SM.
//
// Phase 1:
//   [0      , 8320 )  Ws: W_embed fp16 [16][1040]  (row stride 520 words)
//   [8320   , 26752)  ring: 8 warps x 2304 floats (4 slots x [16][36] fp32)
//                     per-warp scratch overlays ring at +768 after mainloop:
//                     es[16][20] then As_w[16][76]
//   [26752  , 27924)  small weights (W1, Wg, b1, be, bg)
// Phase 2 overlay (after phase-1 consumers are done):
//   [0      , 8976 )  stage: raw fp32 Wc chunk [68][132]
//   [8976   , 14608)  Wc: fp16 [128 n][88 k]  (half2 word index = 44*n + kp)
// ---------------------------------------------------------------------------
#define OFF_WS     0
#define WS_WSTRIDE 520       // unsigned words per Ws row (1040 halfs)
#define OFF_RING   8320
#define RW_FLOATS  2304      // per-warp ring floats
#define SLOT_F     576       // per slot: 16 rows x 36
#define XS_STRIDE  36
#define SCR_OFF    768       // warp scratch offset inside its ring region
#define OFF_SW1    26752
#define OFF_SWG    27776
#define OFF_SB1    27840
#define OFF_SBE    27904
#define OFF_SBG    27920
#define SMEM_FLOATS 27924

#define OFF_STAGE  0
#define STG_STRIDE 132
#define OFF_WC     8976      // floats; as unsigned words: word = 44*n + kp

// ---------------------------------------------------------------------------
// Helpers
// ---------------------------------------------------------------------------
__device__ __forceinline__ unsigned pack_h2(float lo, float hi) {
    unsigned r;   // PTX: first source -> high half
    asm("cvt.rn.f16x2.f32 %0, %1, %2;" : "=r"(r) : "f"(hi), "f"(lo));
    return r;
}

__device__ __forceinline__ void ffma2(unsigned long long& acc,
                                      unsigned long long a,
                                      unsigned long long b) {
    asm("fma.rn.f32x2 %0, %1, %2, %0;" : "+l"(acc) : "l"(a), "l"(b));
}

__device__ __forceinline__ void mma_f16(float* c, const unsigned* a,
                                        unsigned b0, unsigned b1) {
    asm volatile(
        "mma.sync.aligned.m16n8k16.row.col.f32.f16.f16.f32 "
        "{%0,%1,%2,%3}, {%4,%5,%6,%7}, {%8,%9}, {%0,%1,%2,%3};"
        : "+f"(c[0]), "+f"(c[1]), "+f"(c[2]), "+f"(c[3])
        : "r"(a[0]), "r"(a[1]), "r"(a[2]), "r"(a[3]), "r"(b0), "r"(b1));
}

__device__ __forceinline__ void cp_async16(float* s, const float* g) {
    unsigned sa = (unsigned)__cvta_generic_to_shared(s);
    asm volatile("cp.async.ca.shared.global [%0], [%1], 16;" :: "r"(sa), "l"(g));
}
#define CP_COMMIT() asm volatile("cp.async.commit_group;")
#define CP_WAIT(n)  asm volatile("cp.async.wait_group %0;" :: "n"(n))

// Stage one raw Wc chunk (rows 0..63 = W2 flat, 64..67 = b2) via cp.async.
// Columns clamped to 996 (garbage loaded in-bounds; zeroed at conversion).
__device__ __forceinline__ void issue_stage(float* sm, const float* W2,
                                            const float* b2, int nb, int tid) {
#pragma unroll
    for (int j = 0; j < 9; j++) {
        int i = tid + j * 256;
        if (i < 68 * 33) {
            int r = i / 33, c4 = i % 33;
            int col = nb * 128 + c4 * 4;
            if (col > 996) col = 996;
            const float* src = (r < 64) ? (W2 + r * OUTD + col)
                                        : (b2 + (r - 64) * OUTD + col);
            cp_async16(sm + OFF_STAGE + r * STG_STRIDE + c4 * 4, src);
        }
    }
    CP_COMMIT();
}

// ---------------------------------------------------------------------------
// Fused kernel.  One CTA = 128 batch rows, 256 threads (8 warps), grid 256.
// Each warp owns 16 rows end-to-end: barrier-free phase-1 pipeline, warp-local
// epilogue, A fragments kept in registers for phase 2.
// ---------------------------------------------------------------------------
__global__ void __launch_bounds__(256, 2)
k_fused(const float* __restrict__ x,
        const float* __restrict__ We, const float* __restrict__ be,
        const float* __restrict__ W1, const float* __restrict__ b1,
        const float* __restrict__ W2, const float* __restrict__ b2,
        const float* __restrict__ Wg, const float* __restrict__ bg,
        float* __restrict__ out) {
    extern __shared__ float sm[];
    const int tid  = threadIdx.x;
    const int wid  = tid >> 5, lane = tid & 31;
    const int tig  = lane & 3, grp = lane >> 2;

    float* ringw = sm + OFF_RING + wid * RW_FLOATS;
    const float* xw = x + ((size_t)blockIdx.x * 128 + wid * 16) * XROW;

    // ---- preload x chunks 0..2 into this warp's ring (issued first) ----
#pragma unroll
    for (int s = 0; s < 3; s++) {
        float* slot = ringw + s * SLOT_F;
#pragma unroll
        for (int i = 0; i < 4; i++) {
            int idx = lane + 32 * i;
            int r = idx >> 3, c4 = idx & 7;
            cp_async16(slot + r * XS_STRIDE + c4 * 4,
                       xw + (size_t)r * XROW + s * 32 + c4 * 4);
        }
        CP_COMMIT();
    }

    // ---- small weights ----
    for (int i = tid; i < 1024; i += 256) sm[OFF_SW1 + i] = W1[i];
    if (tid < 64)       sm[OFF_SWG + tid] = Wg[tid];
    else if (tid < 128) sm[OFF_SB1 + tid - 64] = b1[tid - 64];
    else if (tid < 144) sm[OFF_SBE + tid - 128] = be[tid - 128];
    else if (tid < 148) sm[OFF_SBG + tid - 144] = bg[tid - 144];

    // ---- W_embed -> fp16 smem [16][1040] ----
    {
        unsigned* wsu = (unsigned*)(sm + OFF_WS);
        for (int i = tid; i < 4096; i += 256) {
            float4 v = ((const float4*)We)[i];
            int row = i >> 8, c4 = i & 255;
            uint2 p = make_uint2(pack_h2(v.x, v.y), pack_h2(v.z, v.w));
            *(uint2*)&wsu[row * WS_WSTRIDE + c4 * 2] = p;
        }
    }
    __syncthreads();   // Ws + small weights visible

    // ---------------- phase-1 mainloop: barrier-free per warp -------------
    const unsigned* wsu = (const unsigned*)(sm + OFF_WS);
    float c0[4] = {0.f, 0.f, 0.f, 0.f};
    float c1[4] = {0.f, 0.f, 0.f, 0.f};

    for (int kc = 0; kc < 32; kc++) {
        CP_WAIT(2);        // this warp's chunk kc has arrived
        __syncwarp();      // cross-lane visibility + ordering before reuse
        if (kc + 3 < 32) { // refill slot (kc+3)&3 with chunk kc+3
            float* slot = ringw + ((kc + 3) & 3) * SLOT_F;
            const float* src = xw + (size_t)(kc + 3) * 32;
#pragma unroll
            for (int i = 0; i < 4; i++) {
                int idx = lane + 32 * i;
                int r = idx >> 3, c4 = idx & 7;
                cp_async16(slot + r * XS_STRIDE + c4 * 4,
                           src + (size_t)r * XROW + c4 * 4);
            }
        }
        CP_COMMIT();       // unconditional: keeps group arithmetic uniform

        const float* xs = ringw + (kc & 3) * SLOT_F;
#pragma unroll
        for (int s = 0; s < 2; s++) {
            const int k0 = 16 * s + 2 * tig;
            float2 p0 = *(const float2*)(xs + grp * XS_STRIDE + k0);
            float2 p1 = *(const float2*)(xs + (grp + 8) * XS_STRIDE + k0);
            float2 p2 = *(const float2*)(xs + grp * XS_STRIDE + k0 + 8);
            float2 p3 = *(const float2*)(xs + (grp + 8) * XS_STRIDE + k0 + 8);
            unsigned a[4];
            a[0] = pack_h2(p0.x, p0.y);
            a[1] = pack_h2(p1.x, p1.y);
            a[2] = pack_h2(p2.x, p2.y);
            a[3] = pack_h2(p3.x, p3.y);
            const int kw = kc * 16 + 8 * s + tig;
            mma_f16(c0, a, wsu[grp * WS_WSTRIDE + kw],
                           wsu[grp * WS_WSTRIDE + kw + 4]);
            mma_f16(c1, a, wsu[(8 + grp) * WS_WSTRIDE + kw],
                           wsu[(8 + grp) * WS_WSTRIDE + kw + 4]);
        }
    }
    __syncwarp();          // final slot reads done before scratch overlays ring
    __syncthreads();       // everyone done with Ws region
    issue_stage(sm, W2, b2, 0, tid);   // Wc chunk 0 DMA overlaps epilogue

    // ---------------- warp-local epilogue ----------------
    float* es   = ringw + SCR_OFF;          // [16][20]
    float* As_w = ringw + SCR_OFF + 320;    // [16][76]
    {
        int jb = 2 * tig;
        *(float2*)(es + grp * 20 + jb)            = make_float2(c0[0], c0[1]);
        *(float2*)(es + (grp + 8) * 20 + jb)      = make_float2(c0[2], c0[3]);
        *(float2*)(es + grp * 20 + 8 + jb)        = make_float2(c1[0], c1[1]);
        *(float2*)(es + (grp + 8) * 20 + 8 + jb)  = make_float2(c1[2], c1[3]);
    }
    __syncwarp();

    if (lane < 16) {
        const float* sbe = sm + OFF_SBE;
        float e[EMBED];
#pragma unroll
        for (int q = 0; q < 4; q++) {
            float4 v = *(float4*)(es + lane * 20 + q * 4);
            e[q * 4 + 0] = fmaxf(v.x + sbe[q * 4 + 0], 0.f);
            e[q * 4 + 1] = fmaxf(v.y + sbe[q * 4 + 1], 0.f);
            e[q * 4 + 2] = fmaxf(v.z + sbe[q * 4 + 2], 0.f);
            e[q * 4 + 3] = fmaxf(v.w + sbe[q * 4 + 3], 0.f);
        }
        const float* sWg = sm + OFF_SWG;
        const float* sbg = sm + OFF_SBG;
        float g[NEXP];
#pragma unroll
        for (int ex = 0; ex < NEXP; ex++) {
            float s = sbg[ex];
#pragma unroll
            for (int j = 0; j < EMBED; j++) s += e[j] * sWg[ex * EMBED + j];
            g[ex] = s;
        }
        float mx = fmaxf(fmaxf(g[0], g[1]), fmaxf(g[2], g[3]));
        float den = 0.f;
#pragma unroll
        for (int ex = 0; ex < NEXP; ex++) { g[ex] = __expf(g[ex] - mx); den += g[ex]; }
        float inv = 1.0f / den;
#pragma unroll
        for (int ex = 0; ex < NEXP; ex++) g[ex] *= inv;

        float* Arow = As_w + lane * 76;
        const float* sW1 = sm + OFF_SW1;
        const float* sb1 = sm + OFF_SB1;
#pragma unroll
        for (int ex = 0; ex < NEXP; ex++) {
            unsigned long long acc[8];
            const ulonglong2* bp = (const ulonglong2*)(sb1 + ex * TINY);
#pragma unroll
            for (int h = 0; h < 4; h++) {
                ulonglong2 t = bp[h];
                acc[2 * h] = t.x; acc[2 * h + 1] = t.y;
            }
#pragma unroll
            for (int j = 0; j < EMBED; j++) {
                unsigned long long ej2;
                asm("mov.b64 %0, {%1, %1};" : "=l"(ej2) : "f"(e[j]));
                const ulonglong2* wp =
                    (const ulonglong2*)(sW1 + (ex * EMBED + j) * TINY);
#pragma unroll
                for (int h = 0; h < 4; h++) {
                    ulonglong2 w = wp[h];
                    ffma2(acc[2 * h], ej2, w.x);
                    ffma2(acc[2 * h + 1], ej2, w.y);
                }
            }
            float gx = g[ex];
#pragma unroll
            for (int h = 0; h < 8; h++) {
                float lo, hi;
                asm("mov.b64 {%0,%1}, %2;" : "=f"(lo), "=f"(hi) : "l"(acc[h]));
                Arow[ex * TINY + 2 * h]     = fmaxf(lo, 0.f) * gx;
                Arow[ex * TINY + 2 * h + 1] = fmaxf(hi, 0.f) * gx;
            }
        }
        *(float4*)(Arow + 64) = make_float4(g[0], g[1], g[2], g[3]);
        *(float4*)(Arow + 68) = make_float4(0.f, 0.f, 0.f, 0.f);
    }
    __syncwarp();

    // ---- build A fragments in registers (fp16, K padded 72->80) ----
    unsigned af[5][4];
#pragma unroll
    for (int s = 0; s < 5; s++) {
        const int k0 = 16 * s + 2 * tig;
        float2 p0 = *(const float2*)(As_w + grp * 76 + k0);
        float2 p1 = *(const float2*)(As_w + (grp + 8) * 76 + k0);
        af[s][0] = pack_h2(p0.x, p0.y);
        af[s][1] = pack_h2(p1.x, p1.y);
        if (s < 4) {
            float2 p2 = *(const float2*)(As_w + grp * 76 + k0 + 8);
            float2 p3 = *(const float2*)(As_w + (grp + 8) * 76 + k0 + 8);
            af[s][2] = pack_h2(p2.x, p2.y);
            af[s][3] = pack_h2(p3.x, p3.y);
        } else {
            af[s][2] = 0u; af[s][3] = 0u;   // cols 72..79 are zero pad
        }
    }

    CP_WAIT(0);        // stage chunk 0 arrived
    __syncthreads();   // scratch reads done; stage visible; overlays now safe

    // ---------------- phase 2: out = A @ Wc, 8 N-chunks of 128 -------------
    unsigned* wc = (unsigned*)(sm + OFF_WC);
    const int cvt_n  = tid & 127;         // conversion: this thread's n column
    const int cvt_kh = tid >> 7;          // kp half (0: kp 0..19, 1: 20..39)
    const int gr = blockIdx.x * 128 + wid * 16 + grp;

    for (int nb = 0; nb < 8; nb++) {
        // convert stage (fp32 [k][n]) -> Wc (fp16 [n][k]), zero-fill invalid
        {
            const bool valid = (nb * 128 + cvt_n) < OUTD;
            const float* stg = sm + OFF_STAGE + cvt_n;
#pragma unroll
            for (int q = 0; q < 20; q++) {
                int kp = cvt_kh * 20 + q;
                unsigned v = 0u;
                if (valid && kp < 34)
                    v = pack_h2(stg[(2 * kp) * STG_STRIDE],
                                stg[(2 * kp + 1) * STG_STRIDE]);
                wc[44 * cvt_n + kp] = v;
            }
        }
        __syncthreads();                    // Wc ready; stage drained
        if (nb < 7) issue_stage(sm, W2, b2, nb + 1, tid);  // overlap DMA

        float cc[16][4];
#pragma unroll
        for (int n8 = 0; n8 < 16; n8++)
#pragma unroll
            for (int q = 0; q < 4; q++) cc[n8][q] = 0.f;

#pragma unroll
        for (int s = 0; s < 5; s++) {
#pragma unroll
            for (int n8 = 0; n8 < 16; n8++) {
                const int nc = 8 * n8 + grp;
                mma_f16(cc[n8], af[s], wc[44 * nc + 8 * s + tig],
                                       wc[44 * nc + 8 * s + tig + 4]);
            }
        }

        // stores: predicated float2 (OUTD even -> pairs all-or-none)
#pragma unroll
        for (int n8 = 0; n8 < 16; n8++) {
            int gc = nb * 128 + 8 * n8 + 2 * tig;
            if (gc < OUTD) {
                *(float2*)(out + (size_t)gr * OUTD + gc) =
                    make_float2(cc[n8][0], cc[n8][1]);
                *(float2*)(out + (size_t)(gr + 8) * OUTD + gc) =
                    make_float2(cc[n8][2], cc[n8][3]);
            }
        }

        if (nb < 7) {
            CP_WAIT(0);        // next raw chunk arrived
            __syncthreads();   // all Wc reads done before next conversion
        }
    }
}

// ---------------------------------------------------------------------------
// Launch
// ---------------------------------------------------------------------------
extern "C" void kernel_launch(void* const* d_in, const int* in_sizes, int n_in,
                              void* d_out, int out_size) {
    const float* x   = (const float*)d_in[0];
    const float* We  = (const float*)d_in[1];
    const float* be  = (const float*)d_in[2];
    const float* W1  = (const float*)d_in[3];
    const float* b1  = (const float*)d_in[4];
    const float* W2  = (const float*)d_in[5];
    const float* b2  = (const float*)d_in[6];
    const float* Wg  = (const float*)d_in[7];
    const float* bg  = (const float*)d_in[8];
    float* out = (float*)d_out;

    static bool attr_done = false;  // attribute setting only; deterministic
    if (!attr_done) {
        cudaFuncSetAttribute(k_fused, cudaFuncAttributeMaxDynamicSharedMemorySize,
                             SMEM_FLOATS * 4);
        attr_done = true;
    }

    k_fused<<<BATCH / 128, 256, SMEM_FLOATS * 4>>>(x, We, be, W1, b1, W2, b2,
                                                   Wg, bg, out);
}

// round 16
// speedup vs baseline: 1.5827x; 1.2444x over previous
#include <cuda_runtime.h>
#include <cuda_fp16.h>
#include <cstdint>

// ---------------------------------------------------------------------------
// Problem constants
// ---------------------------------------------------------------------------
#define BATCH   32768
#define XROW    3072      // x row stride (3*32*32)
#define EMBED   16
#define TINY    16
#define NEXP    4
#define OUTD    1000

#define THREADS 512       // 16 warps, 256 rows per CTA, 1 CTA/SM (32 warps/SM)

// ---------------------------------------------------------------------------
// smem layout (float offsets).  Total 46356 floats = 185424 B -> 1 CTA/SM.
//
// Phase 1:
//   [0     , 8320 )  Ws: W_embed fp16 [16][1040]  (row stride 520 words)
//   [8320  , 45184)  ring: 16 warps x 2304 floats (4 slots x [16][36] fp32)
//                    per-warp scratch overlays ring at +768 after mainloop:
//                    es[16][20] then As_w[16][76]
//   [45184 , 46356)  small weights (W1, Wg, b1, be, bg)
// Phase 2 overlay (after phase-1 consumers are done):
//   [0     , 8976 )  stage: raw fp32 Wc chunk [68][132]   (< warp0 scratch @9088)
//   [8976  , 14608)  Wc: fp16 [128 n][88 k]  (half2 word index = 44*n + kp)
// ---------------------------------------------------------------------------
#define OFF_WS     0
#define WS_WSTRIDE 520       // unsigned words per Ws row (1040 halfs)
#define OFF_RING   8320
#define RW_FLOATS  2304      // per-warp ring floats
#define SLOT_F     576       // per slot: 16 rows x 36
#define XS_STRIDE  36
#define SCR_OFF    768       // warp scratch offset inside its ring region
#define OFF_SW1    45184
#define OFF_SWG    46208
#define OFF_SB1    46272
#define OFF_SBE    46336
#define OFF_SBG    46352
#define SMEM_FLOATS 46356

#define OFF_STAGE  0
#define STG_STRIDE 132
#define OFF_WC     8976      // floats; as unsigned words: word = 44*n + kp

// ---------------------------------------------------------------------------
// Helpers
// ---------------------------------------------------------------------------
__device__ __forceinline__ unsigned pack_h2(float lo, float hi) {
    unsigned r;   // PTX: first source -> high half
    asm("cvt.rn.f16x2.f32 %0, %1, %2;" : "=r"(r) : "f"(hi), "f"(lo));
    return r;
}

__device__ __forceinline__ void ffma2(unsigned long long& acc,
                                      unsigned long long a,
                                      unsigned long long b) {
    asm("fma.rn.f32x2 %0, %1, %2, %0;" : "+l"(acc) : "l"(a), "l"(b));
}

__device__ __forceinline__ void mma_f16(float* c, const unsigned* a,
                                        unsigned b0, unsigned b1) {
    asm volatile(
        "mma.sync.aligned.m16n8k16.row.col.f32.f16.f16.f32 "
        "{%0,%1,%2,%3}, {%4,%5,%6,%7}, {%8,%9}, {%0,%1,%2,%3};"
        : "+f"(c[0]), "+f"(c[1]), "+f"(c[2]), "+f"(c[3])
        : "r"(a[0]), "r"(a[1]), "r"(a[2]), "r"(a[3]), "r"(b0), "r"(b1));
}

__device__ __forceinline__ void cp_async16(float* s, const float* g) {
    unsigned sa = (unsigned)__cvta_generic_to_shared(s);
    asm volatile("cp.async.ca.shared.global [%0], [%1], 16;" :: "r"(sa), "l"(g));
}
#define CP_COMMIT() asm volatile("cp.async.commit_group;")
#define CP_WAIT(n)  asm volatile("cp.async.wait_group %0;" :: "n"(n))

// Stage one raw Wc chunk (rows 0..63 = W2 flat, 64..67 = b2) via cp.async.
// Columns clamped to 996 (garbage loaded in-bounds; zeroed at conversion).
__device__ __forceinline__ void issue_stage(float* sm, const float* W2,
                                            const float* b2, int nb, int tid) {
#pragma unroll
    for (int j = 0; j < 5; j++) {
        int i = tid + j * THREADS;
        if (i < 68 * 33) {
            int r = i / 33, c4 = i % 33;
            int col = nb * 128 + c4 * 4;
            if (col > 996) col = 996;
            const float* src = (r < 64) ? (W2 + r * OUTD + col)
                                        : (b2 + (r - 64) * OUTD + col);
            cp_async16(sm + OFF_STAGE + r * STG_STRIDE + c4 * 4, src);
        }
    }
    CP_COMMIT();
}

// ---------------------------------------------------------------------------
// Fused kernel.  One CTA = 256 batch rows, 512 threads (16 warps), grid 128.
// Each warp owns 16 rows end-to-end: barrier-free phase-1 pipeline, warp-local
// epilogue, A fragments kept in registers for phase 2.
// ---------------------------------------------------------------------------
__global__ void __launch_bounds__(THREADS, 1)
k_fused(const float* __restrict__ x,
        const float* __restrict__ We, const float* __restrict__ be,
        const float* __restrict__ W1, const float* __restrict__ b1,
        const float* __restrict__ W2, const float* __restrict__ b2,
        const float* __restrict__ Wg, const float* __restrict__ bg,
        float* __restrict__ out) {
    extern __shared__ float sm[];
    const int tid  = threadIdx.x;
    const int wid  = tid >> 5, lane = tid & 31;
    const int tig  = lane & 3, grp = lane >> 2;

    float* ringw = sm + OFF_RING + wid * RW_FLOATS;
    const float* xw = x + ((size_t)blockIdx.x * 256 + wid * 16) * XROW;

    // ---- preload x chunks 0..2 into this warp's ring (issued first) ----
#pragma unroll
    for (int s = 0; s < 3; s++) {
        float* slot = ringw + s * SLOT_F;
#pragma unroll
        for (int i = 0; i < 4; i++) {
            int idx = lane + 32 * i;
            int r = idx >> 3, c4 = idx & 7;
            cp_async16(slot + r * XS_STRIDE + c4 * 4,
                       xw + (size_t)r * XROW + s * 32 + c4 * 4);
        }
        CP_COMMIT();
    }

    // ---- small weights ----
    for (int i = tid; i < 1024; i += THREADS) sm[OFF_SW1 + i] = W1[i];
    if (tid < 64)       sm[OFF_SWG + tid] = Wg[tid];
    else if (tid < 128) sm[OFF_SB1 + tid - 64] = b1[tid - 64];
    else if (tid < 144) sm[OFF_SBE + tid - 128] = be[tid - 128];
    else if (tid < 148) sm[OFF_SBG + tid - 144] = bg[tid - 144];

    // ---- W_embed -> fp16 smem [16][1040] ----
    {
        unsigned* wsu = (unsigned*)(sm + OFF_WS);
        for (int i = tid; i < 4096; i += THREADS) {
            float4 v = ((const float4*)We)[i];
            int row = i >> 8, c4 = i & 255;
            uint2 p = make_uint2(pack_h2(v.x, v.y), pack_h2(v.z, v.w));
            *(uint2*)&wsu[row * WS_WSTRIDE + c4 * 2] = p;
        }
    }
    __syncthreads();   // Ws + small weights visible

    // ---------------- phase-1 mainloop: barrier-free per warp -------------
    const unsigned* wsu = (const unsigned*)(sm + OFF_WS);
    float c0[4] = {0.f, 0.f, 0.f, 0.f};
    float c1[4] = {0.f, 0.f, 0.f, 0.f};

    for (int kc = 0; kc < 32; kc++) {
        CP_WAIT(2);        // this warp's chunk kc has arrived
        __syncwarp();      // cross-lane visibility + ordering before reuse
        if (kc + 3 < 32) { // refill slot (kc+3)&3 with chunk kc+3
            float* slot = ringw + ((kc + 3) & 3) * SLOT_F;
            const float* src = xw + (size_t)(kc + 3) * 32;
#pragma unroll
            for (int i = 0; i < 4; i++) {
                int idx = lane + 32 * i;
                int r = idx >> 3, c4 = idx & 7;
                cp_async16(slot + r * XS_STRIDE + c4 * 4,
                           src + (size_t)r * XROW + c4 * 4);
            }
        }
        CP_COMMIT();       // unconditional: keeps group arithmetic uniform

        const float* xs = ringw + (kc & 3) * SLOT_F;
#pragma unroll
        for (int s = 0; s < 2; s++) {
            const int k0 = 16 * s + 2 * tig;
            float2 p0 = *(const float2*)(xs + grp * XS_STRIDE + k0);
            float2 p1 = *(const float2*)(xs + (grp + 8) * XS_STRIDE + k0);
            float2 p2 = *(const float2*)(xs + grp * XS_STRIDE + k0 + 8);
            float2 p3 = *(const float2*)(xs + (grp + 8) * XS_STRIDE + k0 + 8);
            unsigned a[4];
            a[0] = pack_h2(p0.x, p0.y);
            a[1] = pack_h2(p1.x, p1.y);
            a[2] = pack_h2(p2.x, p2.y);
            a[3] = pack_h2(p3.x, p3.y);
            const int kw = kc * 16 + 8 * s + tig;
            mma_f16(c0, a, wsu[grp * WS_WSTRIDE + kw],
                           wsu[grp * WS_WSTRIDE + kw + 4]);
            mma_f16(c1, a, wsu[(8 + grp) * WS_WSTRIDE + kw],
                           wsu[(8 + grp) * WS_WSTRIDE + kw + 4]);
        }
    }
    __syncwarp();          // final slot reads done before scratch overlays ring
    __syncthreads();       // everyone done with Ws region
    issue_stage(sm, W2, b2, 0, tid);   // Wc chunk 0 DMA overlaps epilogue
                                       // (stage [0,8976) < warp0 scratch @9088)

    // ---------------- warp-local epilogue ----------------
    float* es   = ringw + SCR_OFF;          // [16][20]
    float* As_w = ringw + SCR_OFF + 320;    // [16][76]
    {
        int jb = 2 * tig;
        *(float2*)(es + grp * 20 + jb)            = make_float2(c0[0], c0[1]);
        *(float2*)(es + (grp + 8) * 20 + jb)      = make_float2(c0[2], c0[3]);
        *(float2*)(es + grp * 20 + 8 + jb)        = make_float2(c1[0], c1[1]);
        *(float2*)(es + (grp + 8) * 20 + 8 + jb)  = make_float2(c1[2], c1[3]);
    }
    __syncwarp();

    if (lane < 16) {
        const float* sbe = sm + OFF_SBE;
        float e[EMBED];
#pragma unroll
        for (int q = 0; q < 4; q++) {
            float4 v = *(float4*)(es + lane * 20 + q * 4);
            e[q * 4 + 0] = fmaxf(v.x + sbe[q * 4 + 0], 0.f);
            e[q * 4 + 1] = fmaxf(v.y + sbe[q * 4 + 1], 0.f);
            e[q * 4 + 2] = fmaxf(v.z + sbe[q * 4 + 2], 0.f);
            e[q * 4 + 3] = fmaxf(v.w + sbe[q * 4 + 3], 0.f);
        }
        const float* sWg = sm + OFF_SWG;
        const float* sbg = sm + OFF_SBG;
        float g[NEXP];
#pragma unroll
        for (int ex = 0; ex < NEXP; ex++) {
            float s = sbg[ex];
#pragma unroll
            for (int j = 0; j < EMBED; j++) s += e[j] * sWg[ex * EMBED + j];
            g[ex] = s;
        }
        float mx = fmaxf(fmaxf(g[0], g[1]), fmaxf(g[2], g[3]));
        float den = 0.f;
#pragma unroll
        for (int ex = 0; ex < NEXP; ex++) { g[ex] = __expf(g[ex] - mx); den += g[ex]; }
        float inv = 1.0f / den;
#pragma unroll
        for (int ex = 0; ex < NEXP; ex++) g[ex] *= inv;

        float* Arow = As_w + lane * 76;
        const float* sW1 = sm + OFF_SW1;
        const float* sb1 = sm + OFF_SB1;
#pragma unroll
        for (int ex = 0; ex < NEXP; ex++) {
            unsigned long long acc[8];
            const ulonglong2* bp = (const ulonglong2*)(sb1 + ex * TINY);
#pragma unroll
            for (int h = 0; h < 4; h++) {
                ulonglong2 t = bp[h];
                acc[2 * h] = t.x; acc[2 * h + 1] = t.y;
            }
#pragma unroll
            for (int j = 0; j < EMBED; j++) {
                unsigned long long ej2;
                asm("mov.b64 %0, {%1, %1};" : "=l"(ej2) : "f"(e[j]));
                const ulonglong2* wp =
                    (const ulonglong2*)(sW1 + (ex * EMBED + j) * TINY);
#pragma unroll
                for (int h = 0; h < 4; h++) {
                    ulonglong2 w = wp[h];
                    ffma2(acc[2 * h], ej2, w.x);
                    ffma2(acc[2 * h + 1], ej2, w.y);
                }
            }
            float gx = g[ex];
#pragma unroll
            for (int h = 0; h < 8; h++) {
                float lo, hi;
                asm("mov.b64 {%0,%1}, %2;" : "=f"(lo), "=f"(hi) : "l"(acc[h]));
                Arow[ex * TINY + 2 * h]     = fmaxf(lo, 0.f) * gx;
                Arow[ex * TINY + 2 * h + 1] = fmaxf(hi, 0.f) * gx;
            }
        }
        *(float4*)(Arow + 64) = make_float4(g[0], g[1], g[2], g[3]);
        *(float4*)(Arow + 68) = make_float4(0.f, 0.f, 0.f, 0.f);
    }
    __syncwarp();

    // ---- build A fragments in registers (fp16, K padded 72->80) ----
    unsigned af[5][4];
#pragma unroll
    for (int s = 0; s < 5; s++) {
        const int k0 = 16 * s + 2 * tig;
        float2 p0 = *(const float2*)(As_w + grp * 76 + k0);
        float2 p1 = *(const float2*)(As_w + (grp + 8) * 76 + k0);
        af[s][0] = pack_h2(p0.x, p0.y);
        af[s][1] = pack_h2(p1.x, p1.y);
        if (s < 4) {
            float2 p2 = *(const float2*)(As_w + grp * 76 + k0 + 8);
            float2 p3 = *(const float2*)(As_w + (grp + 8) * 76 + k0 + 8);
            af[s][2] = pack_h2(p2.x, p2.y);
            af[s][3] = pack_h2(p3.x, p3.y);
        } else {
            af[s][2] = 0u; af[s][3] = 0u;   // cols 72..79 are zero pad
        }
    }

    CP_WAIT(0);        // stage chunk 0 arrived
    __syncthreads();   // scratch reads done; stage visible; overlays now safe

    // ---------------- phase 2: out = A @ Wc, 8 N-chunks of 128 -------------
    unsigned* wc = (unsigned*)(sm + OFF_WC);
    const int cvt_n  = tid & 127;         // conversion: this thread's n column
    const int cvt_kh = tid >> 7;          // kp quarter (10 kp values each)
    const int gr = blockIdx.x * 256 + wid * 16 + grp;

    for (int nb = 0; nb < 8; nb++) {
        // convert stage (fp32 [k][n]) -> Wc (fp16 [n][k]), zero-fill invalid
        {
            const bool valid = (nb * 128 + cvt_n) < OUTD;
            const float* stg = sm + OFF_STAGE + cvt_n;
#pragma unroll
            for (int q = 0; q < 10; q++) {
                int kp = cvt_kh * 10 + q;
                unsigned v = 0u;
                if (valid && kp < 34)
                    v = pack_h2(stg[(2 * kp) * STG_STRIDE],
                                stg[(2 * kp + 1) * STG_STRIDE]);
                wc[44 * cvt_n + kp] = v;
            }
        }
        __syncthreads();                    // Wc ready; stage drained
        if (nb < 7) issue_stage(sm, W2, b2, nb + 1, tid);  // overlap DMA

        // two N-halves of 64 cols: 32 live accumulators instead of 64
#pragma unroll
        for (int half = 0; half < 2; half++) {
            float cc[8][4];
#pragma unroll
            for (int n8 = 0; n8 < 8; n8++)
#pragma unroll
                for (int q = 0; q < 4; q++) cc[n8][q] = 0.f;

#pragma unroll
            for (int s = 0; s < 5; s++) {
#pragma unroll
                for (int n8 = 0; n8 < 8; n8++) {
                    const int nc = 64 * half + 8 * n8 + grp;
                    mma_f16(cc[n8], af[s], wc[44 * nc + 8 * s + tig],
                                           wc[44 * nc + 8 * s + tig + 4]);
                }
            }
            // stores: predicated float2 (OUTD even -> pairs all-or-none)
#pragma unroll
            for (int n8 = 0; n8 < 8; n8++) {
                int gc = nb * 128 + 64 * half + 8 * n8 + 2 * tig;
                if (gc < OUTD) {
                    *(float2*)(out + (size_t)gr * OUTD + gc) =
                        make_float2(cc[n8][0], cc[n8][1]);
                    *(float2*)(out + (size_t)(gr + 8) * OUTD + gc) =
                        make_float2(cc[n8][2], cc[n8][3]);
                }
            }
        }

        if (nb < 7) {
            CP_WAIT(0);        // next raw chunk arrived
            __syncthreads();   // all Wc reads done before next conversion
        }
    }
}

// ---------------------------------------------------------------------------
// Launch
// ---------------------------------------------------------------------------
extern "C" void kernel_launch(void* const* d_in, const int* in_sizes, int n_in,
                              void* d_out, int out_size) {
    const float* x   = (const float*)d_in[0];
    const float* We  = (const float*)d_in[1];
    const float* be  = (const float*)d_in[2];
    const float* W1  = (const float*)d_in[3];
    const float* b1  = (const float*)d_in[4];
    const float* W2  = (const float*)d_in[5];
    const float* b2  = (const float*)d_in[6];
    const float* Wg  = (const float*)d_in[7];
    const float* bg  = (const float*)d_in[8];
    float* out = (float*)d_out;

    static bool attr_done = false;  // attribute setting only; deterministic
    if (!attr_done) {
        cudaFuncSetAttribute(k_fused, cudaFuncAttributeMaxDynamicSharedMemorySize,
                             SMEM_FLOATS * 4);
        attr_done = true;
    }

    k_fused<<<BATCH / 256, THREADS, SMEM_FLOATS * 4>>>(x, We, be, W1, b1,
                                                       W2, b2, Wg, bg, out);
}